// round 1
// baseline (speedup 1.0000x reference)
#include <cuda_runtime.h>
#include <cuda_bf16.h>

#define BB 256
#define TT 64
#define DD 2048
#define THRESHOLD 0.99f
#define EPSILON 0.01f

// Grid: (2, BB). blockIdx.x = D-chunk (1024 floats each), blockIdx.y = batch.
// Block: 256 threads, each owns one float4 (4 floats) of the D dimension.
__global__ void __launch_bounds__(256) act_halting_kernel(
    const float* __restrict__ halt_probs,   // [B, T] (trailing dim 1 squeezed)
    const float* __restrict__ outputs,      // [B, T, D]
    const float* __restrict__ step_weights, // [B, T]
    float* __restrict__ out)                // [B*D] ++ [B] ++ [B*T]
{
    const int b     = blockIdx.y;
    const int chunk = blockIdx.x;
    const int tid   = threadIdx.x;

    __shared__ float hp[TT];
    __shared__ float stw[TT];
    __shared__ float sw[TT];
    __shared__ int   s_hs;
    __shared__ float s_ponder;

    if (tid < TT) {
        hp[tid]  = halt_probs[b * TT + tid];
        stw[tid] = step_weights[b * TT + tid];
    }
    __syncthreads();

    if (tid == 0) {
        // Serial scan over T=64: find first t where cumsum >= THRESHOLD.
        float cum = 0.0f;
        int   hs  = TT - 1;
        bool  found = false;
        float cum_at = 0.0f, p_at = 0.0f;
        #pragma unroll
        for (int t = 0; t < TT; ++t) {
            float p = hp[t];
            cum += p;
            if (!found && cum >= THRESHOLD) {
                found = true; hs = t; cum_at = cum; p_at = p;
            }
        }
        if (!found) { hs = TT - 1; cum_at = cum; p_at = hp[TT - 1]; }

        float remaining = 1.0f - cum_at + p_at;

        float sum = 0.0f;
        #pragma unroll
        for (int t = 0; t < TT; ++t) {
            float w = (t < hs) ? hp[t] : ((t == hs) ? remaining : 0.0f);
            w *= stw[t];
            sw[t] = w;
            sum += w;
        }
        sum = fmaxf(sum, EPSILON);
        float inv = 1.0f / sum;

        float ponder = 0.0f;
        #pragma unroll
        for (int t = 0; t < TT; ++t) {
            float w = sw[t] * inv;
            sw[t] = w;
            ponder += w * (float)(t + 1);
        }
        s_hs = hs;
        s_ponder = ponder;
    }
    __syncthreads();

    const int hs = s_hs;

    // Weighted sum over t = 0..hs only (weights are exactly 0 after hs).
    const float4* base = reinterpret_cast<const float4*>(outputs)
                       + (size_t)b * TT * (DD / 4) + chunk * 256 + tid;
    float4 acc = make_float4(0.f, 0.f, 0.f, 0.f);
    for (int t = 0; t <= hs; ++t) {
        float  w = sw[t];
        float4 v = base[(size_t)t * (DD / 4)];
        acc.x = fmaf(w, v.x, acc.x);
        acc.y = fmaf(w, v.y, acc.y);
        acc.z = fmaf(w, v.z, acc.z);
        acc.w = fmaf(w, v.w, acc.w);
    }
    reinterpret_cast<float4*>(out)[(size_t)b * (DD / 4) + chunk * 256 + tid] = acc;

    // Chunk-0 block also writes ponder_cost and the normalized weight row.
    if (chunk == 0) {
        if (tid == 0) out[BB * DD + b] = s_ponder;
        if (tid < TT) out[BB * DD + BB + b * TT + tid] = sw[tid];
    }
}

extern "C" void kernel_launch(void* const* d_in, const int* in_sizes, int n_in,
                              void* d_out, int out_size) {
    const float* halt_probs   = (const float*)d_in[0]; // [B,T,1] = 16384
    const float* outputs      = (const float*)d_in[1]; // [B,T,D] = 33554432
    const float* step_weights = (const float*)d_in[2]; // [B,T]   = 16384
    float* out = (float*)d_out;

    dim3 grid(2, BB);
    act_halting_kernel<<<grid, 256>>>(halt_probs, outputs, step_weights, out);
}

// round 2
// speedup vs baseline: 1.8843x; 1.8843x over previous
#include <cuda_runtime.h>
#include <cuda_bf16.h>

#define BB 256
#define TT 64
#define DD 2048
#define THRESHOLD 0.99f
#define EPSILON 0.01f
#define FULLM 0xffffffffu

// Grid: (2, BB). blockIdx.x = D-chunk (1024 floats), blockIdx.y = batch.
// Block: 256 threads; warp 0 computes the ACT weights with a warp-parallel scan.
__global__ void __launch_bounds__(256) act_halting_kernel(
    const float* __restrict__ halt_probs,   // [B, T] (trailing 1 squeezed)
    const float* __restrict__ outputs,      // [B, T, D]
    const float* __restrict__ step_weights, // [B, T]
    float* __restrict__ out)                // [B*D] ++ [B] ++ [B*T]
{
    const int b     = blockIdx.y;
    const int chunk = blockIdx.x;
    const int tid   = threadIdx.x;

    __shared__ float sw[TT];
    __shared__ int   s_hs;

    if (tid < 32) {
        const int lane = tid;
        // Each lane owns t = lane and t = lane + 32.
        float p_lo = halt_probs[b * TT + lane];
        float p_hi = halt_probs[b * TT + 32 + lane];
        float sw_lo = step_weights[b * TT + lane];
        float sw_hi = step_weights[b * TT + 32 + lane];

        // Two interleaved warp inclusive scans (independent -> overlapped latency).
        float c_lo = p_lo, c_hi = p_hi;
        #pragma unroll
        for (int o = 1; o < 32; o <<= 1) {
            float u = __shfl_up_sync(FULLM, c_lo, o);
            float v = __shfl_up_sync(FULLM, c_hi, o);
            if (lane >= o) { c_lo += u; c_hi += v; }
        }
        float tot_lo = __shfl_sync(FULLM, c_lo, 31);
        c_hi += tot_lo;   // cumsum for t in [32, 64)

        unsigned bl = __ballot_sync(FULLM, c_lo >= THRESHOLD);
        unsigned bh = __ballot_sync(FULLM, c_hi >= THRESHOLD);
        int hs;
        if (bl)       hs = __ffs(bl) - 1;
        else if (bh)  hs = 32 + __ffs(bh) - 1;
        else          hs = TT - 1;

        const int src = hs & 31;
        float cum_lo_at = __shfl_sync(FULLM, c_lo, src);
        float cum_hi_at = __shfl_sync(FULLM, c_hi, src);
        float p_lo_at   = __shfl_sync(FULLM, p_lo, src);
        float p_hi_at   = __shfl_sync(FULLM, p_hi, src);
        float cum_at = (hs < 32) ? cum_lo_at : cum_hi_at;
        float p_at   = (hs < 32) ? p_lo_at   : p_hi_at;
        float remaining = 1.0f - cum_at + p_at;

        const int t_lo = lane, t_hi = lane + 32;
        float w0 = (t_lo < hs) ? p_lo : ((t_lo == hs) ? remaining : 0.0f);
        float w1 = (t_hi < hs) ? p_hi : ((t_hi == hs) ? remaining : 0.0f);
        w0 *= sw_lo;
        w1 *= sw_hi;

        float s = w0 + w1;
        #pragma unroll
        for (int o = 16; o; o >>= 1) s += __shfl_xor_sync(FULLM, s, o);
        float inv = 1.0f / fmaxf(s, EPSILON);
        w0 *= inv;
        w1 *= inv;

        sw[lane]      = w0;
        sw[lane + 32] = w1;
        if (lane == 0) s_hs = hs;

        if (chunk == 0) {
            float pd = w0 * (float)(t_lo + 1) + w1 * (float)(t_hi + 1);
            #pragma unroll
            for (int o = 16; o; o >>= 1) pd += __shfl_xor_sync(FULLM, pd, o);
            if (lane == 0) out[BB * DD + b] = pd;
            out[BB * DD + BB + b * TT + lane]      = w0;
            out[BB * DD + BB + b * TT + 32 + lane] = w1;
        }
    }
    __syncthreads();

    const int hs = s_hs;

    // Weighted sum over t = 0..hs (weights are exactly 0 after hs).
    // Unroll-by-4 with predication: 4 independent loads in flight.
    const float4* base = reinterpret_cast<const float4*>(outputs)
                       + (size_t)b * TT * (DD / 4) + chunk * 256 + tid;
    float4 acc = make_float4(0.f, 0.f, 0.f, 0.f);
    for (int t0 = 0; t0 < TT; t0 += 4) {
        if (t0 > hs) break;
        #pragma unroll
        for (int j = 0; j < 4; ++j) {
            const int t = t0 + j;
            if (t <= hs) {
                float  w = sw[t];
                float4 v = base[(size_t)t * (DD / 4)];
                acc.x = fmaf(w, v.x, acc.x);
                acc.y = fmaf(w, v.y, acc.y);
                acc.z = fmaf(w, v.z, acc.z);
                acc.w = fmaf(w, v.w, acc.w);
            }
        }
    }
    reinterpret_cast<float4*>(out)[(size_t)b * (DD / 4) + chunk * 256 + tid] = acc;
}

extern "C" void kernel_launch(void* const* d_in, const int* in_sizes, int n_in,
                              void* d_out, int out_size) {
    const float* halt_probs   = (const float*)d_in[0]; // [B,T,1] = 16384
    const float* outputs      = (const float*)d_in[1]; // [B,T,D] = 33554432
    const float* step_weights = (const float*)d_in[2]; // [B,T]   = 16384
    float* out = (float*)d_out;

    dim3 grid(2, BB);
    act_halting_kernel<<<grid, 256>>>(halt_probs, outputs, step_weights, out);
}

// round 4
// speedup vs baseline: 1.8930x; 1.0047x over previous
#include <cuda_runtime.h>
#include <cuda_bf16.h>

#define BB 256
#define TT 64
#define DD 2048
#define THRESHOLD 0.99f
#define EPSILON 0.01f
#define FULLM 0xffffffffu

// Grid: BB blocks (one per batch), 512 threads each; thread owns one float4 of D.
// Warp 0 computes ACT weights with a warp-parallel scan while ALL threads'
// speculative loads of rows t=0..3 (96% coverage) are already in flight.
__global__ void __launch_bounds__(512) act_halting_kernel(
    const float* __restrict__ halt_probs,   // [B, T]
    const float* __restrict__ outputs,      // [B, T, D]
    const float* __restrict__ step_weights, // [B, T]
    float* __restrict__ out)                // [B*D] ++ [B] ++ [B*T]
{
    const int b   = blockIdx.x;
    const int tid = threadIdx.x;

    __shared__ float sw[TT];
    __shared__ int   s_hs;

    // ---- Speculative loads: rows 0..3 of this batch, issued FIRST. ----
    const float4* base = reinterpret_cast<const float4*>(outputs)
                       + (size_t)b * TT * (DD / 4) + tid;
    float4 v0 = base[0 * (DD / 4)];
    float4 v1 = base[1 * (DD / 4)];
    float4 v2 = base[2 * (DD / 4)];
    float4 v3 = base[3 * (DD / 4)];

    // ---- Warp 0: weight computation (overlaps the loads above). ----
    if (tid < 32) {
        const int lane = tid;
        float p_lo  = halt_probs[b * TT + lane];
        float p_hi  = halt_probs[b * TT + 32 + lane];
        float sw_lo = step_weights[b * TT + lane];
        float sw_hi = step_weights[b * TT + 32 + lane];

        float c_lo = p_lo, c_hi = p_hi;
        #pragma unroll
        for (int o = 1; o < 32; o <<= 1) {
            float u = __shfl_up_sync(FULLM, c_lo, o);
            float v = __shfl_up_sync(FULLM, c_hi, o);
            if (lane >= o) { c_lo += u; c_hi += v; }
        }
        float tot_lo = __shfl_sync(FULLM, c_lo, 31);
        c_hi += tot_lo;

        unsigned bl = __ballot_sync(FULLM, c_lo >= THRESHOLD);
        unsigned bh = __ballot_sync(FULLM, c_hi >= THRESHOLD);
        int hs;
        if (bl)      hs = __ffs(bl) - 1;
        else if (bh) hs = 32 + __ffs(bh) - 1;
        else         hs = TT - 1;

        const int src = hs & 31;
        float cum_lo_at = __shfl_sync(FULLM, c_lo, src);
        float cum_hi_at = __shfl_sync(FULLM, c_hi, src);
        float p_lo_at   = __shfl_sync(FULLM, p_lo, src);
        float p_hi_at   = __shfl_sync(FULLM, p_hi, src);
        float cum_at = (hs < 32) ? cum_lo_at : cum_hi_at;
        float p_at   = (hs < 32) ? p_lo_at   : p_hi_at;
        float remaining = 1.0f - cum_at + p_at;

        const int t_lo = lane, t_hi = lane + 32;
        float w0 = (t_lo < hs) ? p_lo : ((t_lo == hs) ? remaining : 0.0f);
        float w1 = (t_hi < hs) ? p_hi : ((t_hi == hs) ? remaining : 0.0f);
        w0 *= sw_lo;
        w1 *= sw_hi;

        float s = w0 + w1;
        #pragma unroll
        for (int o = 16; o; o >>= 1) s += __shfl_xor_sync(FULLM, s, o);
        float inv = 1.0f / fmaxf(s, EPSILON);
        w0 *= inv;
        w1 *= inv;

        sw[lane]      = w0;
        sw[lane + 32] = w1;
        if (lane == 0) s_hs = hs;

        // ponder_cost + normalized weights (side outputs)
        float pd = w0 * (float)(t_lo + 1) + w1 * (float)(t_hi + 1);
        #pragma unroll
        for (int o = 16; o; o >>= 1) pd += __shfl_xor_sync(FULLM, pd, o);
        if (lane == 0) out[BB * DD + b] = pd;
        out[BB * DD + BB + b * TT + lane]      = w0;
        out[BB * DD + BB + b * TT + 32 + lane] = w1;
    }
    __syncthreads();

    const int hs = s_hs;

    // sw[t] == 0 for t > hs, so the speculative rows need no predication.
    float4 acc;
    {
        float w0 = sw[0], w1 = sw[1], w2 = sw[2], w3 = sw[3];
        acc.x = w0 * v0.x + w1 * v1.x + w2 * v2.x + w3 * v3.x;
        acc.y = w0 * v0.y + w1 * v1.y + w2 * v2.y + w3 * v3.y;
        acc.z = w0 * v0.z + w1 * v1.z + w2 * v2.z + w3 * v3.z;
        acc.w = w0 * v0.w + w1 * v1.w + w2 * v2.w + w3 * v3.w;
    }

    // Rare tail: hs >= 4 (~4% of batches).
    for (int t0 = 4; t0 <= hs; t0 += 4) {
        #pragma unroll
        for (int j = 0; j < 4; ++j) {
            const int t = t0 + j;
            if (t <= hs) {
                float  w = sw[t];
                float4 v = base[(size_t)t * (DD / 4)];
                acc.x = fmaf(w, v.x, acc.x);
                acc.y = fmaf(w, v.y, acc.y);
                acc.z = fmaf(w, v.z, acc.z);
                acc.w = fmaf(w, v.w, acc.w);
            }
        }
    }
    reinterpret_cast<float4*>(out)[(size_t)b * (DD / 4) + tid] = acc;
}

extern "C" void kernel_launch(void* const* d_in, const int* in_sizes, int n_in,
                              void* d_out, int out_size) {
    const float* halt_probs   = (const float*)d_in[0]; // [B,T,1] = 16384
    const float* outputs      = (const float*)d_in[1]; // [B,T,D] = 33554432
    const float* step_weights = (const float*)d_in[2]; // [B,T]   = 16384
    float* out = (float*)d_out;

    act_halting_kernel<<<BB, 512>>>(halt_probs, outputs, step_weights, out);
}

// round 7
// speedup vs baseline: 1.9662x; 1.0386x over previous
#include <cuda_runtime.h>
#include <cuda_bf16.h>

#define BB 256
#define TT 64
#define DD 2048
#define THRESHOLD 0.99f
#define EPSILON 0.01f
#define FULLM 0xffffffffu

// Grid: BB blocks (one per batch), 512 threads; each thread owns one float4 of D.
// Warp 0 computes the ACT weights (its tiny hp/sw loads are issued FIRST so they
// are not queued behind the block's speculative float4 traffic); weights are
// broadcast through shared memory with a single __syncthreads.
__global__ void __launch_bounds__(512) act_halting_kernel(
    const float* __restrict__ halt_probs,   // [B, T]
    const float* __restrict__ outputs,      // [B, T, D]
    const float* __restrict__ step_weights, // [B, T]
    float* __restrict__ out)                // [B*D] ++ [B] ++ [B*T]
{
    const int b   = blockIdx.x;
    const int tid = threadIdx.x;

    __shared__ float sw[TT];
    __shared__ int   s_hs;

    // ---- 1) Warp 0's scan-dependency loads go FIRST (head of L1tex queue). ----
    float p_lo = 0.f, p_hi = 0.f, sw_lo = 0.f, sw_hi = 0.f;
    if (tid < 32) {
        const float* hpb = halt_probs   + b * TT;
        const float* swb = step_weights + b * TT;
        p_lo  = hpb[tid];
        p_hi  = hpb[32 + tid];
        sw_lo = swb[tid];
        sw_hi = swb[32 + tid];
    }

    // ---- 2) Speculative row loads t=0..3 (96% coverage), overlap the scan. ----
    const float4* base = reinterpret_cast<const float4*>(outputs)
                       + (size_t)b * TT * (DD / 4) + tid;
    float4 v0 = base[0 * (DD / 4)];
    float4 v1 = base[1 * (DD / 4)];
    float4 v2 = base[2 * (DD / 4)];
    float4 v3 = base[3 * (DD / 4)];

    // ---- 3) Warp 0: warp-parallel scan + weight computation. ----
    if (tid < 32) {
        const int lane = tid;

        float c_lo = p_lo, c_hi = p_hi;
        #pragma unroll
        for (int o = 1; o < 32; o <<= 1) {
            float u = __shfl_up_sync(FULLM, c_lo, o);
            float v = __shfl_up_sync(FULLM, c_hi, o);
            if (lane >= o) { c_lo += u; c_hi += v; }
        }
        float tot_lo = __shfl_sync(FULLM, c_lo, 31);
        c_hi += tot_lo;

        unsigned bl = __ballot_sync(FULLM, c_lo >= THRESHOLD);
        unsigned bh = __ballot_sync(FULLM, c_hi >= THRESHOLD);
        int hs;
        if (bl)      hs = __ffs(bl) - 1;
        else if (bh) hs = 32 + __ffs(bh) - 1;
        else         hs = TT - 1;

        const int src = hs & 31;
        float cum_lo_at = __shfl_sync(FULLM, c_lo, src);
        float cum_hi_at = __shfl_sync(FULLM, c_hi, src);
        float p_lo_at   = __shfl_sync(FULLM, p_lo, src);
        float p_hi_at   = __shfl_sync(FULLM, p_hi, src);
        float cum_at = (hs < 32) ? cum_lo_at : cum_hi_at;
        float p_at   = (hs < 32) ? p_lo_at   : p_hi_at;
        float remaining = 1.0f - cum_at + p_at;

        const int t_lo = lane, t_hi = lane + 32;
        float w0 = (t_lo < hs) ? p_lo : ((t_lo == hs) ? remaining : 0.0f);
        float w1 = (t_hi < hs) ? p_hi : ((t_hi == hs) ? remaining : 0.0f);
        w0 *= sw_lo;
        w1 *= sw_hi;

        float s = w0 + w1;
        #pragma unroll
        for (int o = 16; o; o >>= 1) s += __shfl_xor_sync(FULLM, s, o);
        float inv = 1.0f / fmaxf(s, EPSILON);
        w0 *= inv;
        w1 *= inv;

        sw[lane]      = w0;
        sw[lane + 32] = w1;
        if (lane == 0) s_hs = hs;

        // Side outputs: ponder_cost + normalized weight row.
        float pd = w0 * (float)(t_lo + 1) + w1 * (float)(t_hi + 1);
        #pragma unroll
        for (int o = 16; o; o >>= 1) pd += __shfl_xor_sync(FULLM, pd, o);
        if (lane == 0) out[BB * DD + b] = pd;
        out[BB * DD + BB + b * TT + lane]      = w0;
        out[BB * DD + BB + b * TT + 32 + lane] = w1;
    }
    __syncthreads();

    const int hs = s_hs;

    // ---- 4) Weighted sum. sw[t] == 0 for t > hs -> speculative rows need
    //         no predication. ----
    float4 acc;
    {
        float w0 = sw[0], w1 = sw[1], w2 = sw[2], w3 = sw[3];
        acc.x = w0 * v0.x + w1 * v1.x + w2 * v2.x + w3 * v3.x;
        acc.y = w0 * v0.y + w1 * v1.y + w2 * v2.y + w3 * v3.y;
        acc.z = w0 * v0.z + w1 * v1.z + w2 * v2.z + w3 * v3.z;
        acc.w = w0 * v0.w + w1 * v1.w + w2 * v2.w + w3 * v3.w;
    }

    // Uncommon tail hs in [4,7] (~4% of batches): 4 INDEPENDENT predicated loads.
    if (hs >= 4) {
        float4 v4 = make_float4(0,0,0,0), v5 = v4, v6 = v4, v7 = v4;
        if (hs >= 4) v4 = base[4 * (DD / 4)];
        if (hs >= 5) v5 = base[5 * (DD / 4)];
        if (hs >= 6) v6 = base[6 * (DD / 4)];
        if (hs >= 7) v7 = base[7 * (DD / 4)];
        float w4 = sw[4], w5 = sw[5], w6 = sw[6], w7 = sw[7];
        acc.x += w4 * v4.x + w5 * v5.x + w6 * v6.x + w7 * v7.x;
        acc.y += w4 * v4.y + w5 * v5.y + w6 * v6.y + w7 * v7.y;
        acc.z += w4 * v4.z + w5 * v5.z + w6 * v6.z + w7 * v7.z;
        acc.w += w4 * v4.w + w5 * v5.w + w6 * v6.w + w7 * v7.w;

        // Astronomically rare (P ~ 2e-6 per batch) but must be correct.
        for (int t = 8; t <= hs; ++t) {
            float  w = sw[t];
            float4 v = base[(size_t)t * (DD / 4)];
            acc.x = fmaf(w, v.x, acc.x);
            acc.y = fmaf(w, v.y, acc.y);
            acc.z = fmaf(w, v.z, acc.z);
            acc.w = fmaf(w, v.w, acc.w);
        }
    }

    reinterpret_cast<float4*>(out)[(size_t)b * (DD / 4) + tid] = acc;
}

extern "C" void kernel_launch(void* const* d_in, const int* in_sizes, int n_in,
                              void* d_out, int out_size) {
    const float* halt_probs   = (const float*)d_in[0]; // [B,T,1] = 16384
    const float* outputs      = (const float*)d_in[1]; // [B,T,D] = 33554432
    const float* step_weights = (const float*)d_in[2]; // [B,T]   = 16384
    float* out = (float*)d_out;

    act_halting_kernel<<<BB, 512>>>(halt_probs, outputs, step_weights, out);
}